// round 1
// baseline (speedup 1.0000x reference)
#include <cuda_runtime.h>

// Gegenbauer (alpha=0.5 -> Legendre) embedding: out[row, i-1] = C_i(x[row]), i=1..64.
// Store-bound: 512MB output. One thread per row, recurrence in registers,
// 16x float4 stores per row.

#define DIM_OUT 64

__global__ void __launch_bounds__(256) geg_kernel(const float* __restrict__ x,
                                                  float* __restrict__ out,
                                                  int n) {
    int row = blockIdx.x * blockDim.x + threadIdx.x;
    if (row >= n) return;

    float xv = x[row];

    float c[DIM_OUT];
    // alpha = 0.5: C0 = 1, C1 = 2*alpha*x = x
    float prev2 = 1.0f;
    float prev  = xv;
    c[0] = xv;

    // C_i = ((2i-1)*x*C_{i-1} + (1-i)*C_{i-2}) / i   (alpha = 0.5)
    // Fully unrolled: A, B, 1/i all fold to immediates.
    #pragma unroll
    for (int i = 2; i <= DIM_OUT; ++i) {
        float A = (float)(2 * i - 1);
        float B = (float)(1 - i);
        float r = 1.0f / (float)i;
        float ci = (A * xv * prev + B * prev2) * r;
        c[i - 1] = ci;
        prev2 = prev;
        prev  = ci;
    }

    float4* o = reinterpret_cast<float4*>(out + (size_t)row * DIM_OUT);
    #pragma unroll
    for (int j = 0; j < DIM_OUT / 4; ++j) {
        o[j] = make_float4(c[4 * j + 0], c[4 * j + 1], c[4 * j + 2], c[4 * j + 3]);
    }
}

extern "C" void kernel_launch(void* const* d_in, const int* in_sizes, int n_in,
                              void* d_out, int out_size) {
    const float* x = (const float*)d_in[0];
    float* out = (float*)d_out;
    int n = in_sizes[0];   // 2,000,000 rows
    int threads = 256;
    int blocks = (n + threads - 1) / threads;
    geg_kernel<<<blocks, threads>>>(x, out, n);
}

// round 2
// speedup vs baseline: 3.2008x; 3.2008x over previous
#include <cuda_runtime.h>

// Gegenbauer (alpha=0.5 -> Legendre) embedding: out[row, i-1] = C_i(x[row]), i=1..64.
// Store-bound: 512MB output. Round 2: shared-memory staging so the global
// stores are fully coalesced (consecutive lanes -> consecutive float4s).

#define DIM_OUT 64
#define ROWS_PER_BLOCK 128
#define PAD_F4 17              // 68 floats per row in smem: 16B-aligned, conflict-free

__global__ void __launch_bounds__(ROWS_PER_BLOCK) geg_kernel(const float* __restrict__ x,
                                                             float* __restrict__ out,
                                                             int n) {
    __shared__ float4 s[ROWS_PER_BLOCK * PAD_F4];   // 34,816 B

    const int tid = threadIdx.x;
    const int row = blockIdx.x * ROWS_PER_BLOCK + tid;

    if (row < n) {
        const float xv = x[row];

        float c[DIM_OUT];
        // alpha = 0.5: C0 = 1, C1 = x
        float prev2 = 1.0f;
        float prev  = xv;
        c[0] = xv;

        // C_i = ((2i-1)*x*C_{i-1} + (1-i)*C_{i-2}) * (1/i)
        // Fully unrolled: all constants fold to immediates.
        #pragma unroll
        for (int i = 2; i <= DIM_OUT; ++i) {
            const float A = (float)(2 * i - 1);
            const float B = (float)(1 - i);
            const float r = 1.0f / (float)i;
            const float ci = (A * xv * prev + B * prev2) * r;
            c[i - 1] = ci;
            prev2 = prev;
            prev  = ci;
        }

        // Stage into smem, row stride 17 float4 (68 floats).
        #pragma unroll
        for (int j = 0; j < DIM_OUT / 4; ++j) {
            s[tid * PAD_F4 + j] = make_float4(c[4 * j + 0], c[4 * j + 1],
                                              c[4 * j + 2], c[4 * j + 3]);
        }
    }
    __syncthreads();

    // Coalesced copy-out: block owns ROWS_PER_BLOCK*64 floats = 2048 float4s,
    // 128 threads -> 16 float4 per thread, consecutive lanes write consecutive
    // 16B chunks (each warp STG.128 = 512B contiguous, full lines).
    const size_t blk_base_f4 = (size_t)blockIdx.x * (ROWS_PER_BLOCK * DIM_OUT / 4);
    float4* __restrict__ o4 = reinterpret_cast<float4*>(out);
    const size_t total_f4 = ((size_t)n * DIM_OUT) / 4;

    #pragma unroll
    for (int it = 0; it < (ROWS_PER_BLOCK * DIM_OUT / 4) / ROWS_PER_BLOCK; ++it) {
        const int f = it * ROWS_PER_BLOCK + tid;       // float4 index within block tile
        const int r = f >> 4;                          // row within block (64 floats = 16 f4)
        const int cq = f & 15;                         // float4 column within row
        const size_t g = blk_base_f4 + f;
        if (g < total_f4) {
            o4[g] = s[r * PAD_F4 + cq];
        }
    }
}

extern "C" void kernel_launch(void* const* d_in, const int* in_sizes, int n_in,
                              void* d_out, int out_size) {
    const float* x = (const float*)d_in[0];
    float* out = (float*)d_out;
    int n = in_sizes[0];   // 2,000,000 rows
    int blocks = (n + ROWS_PER_BLOCK - 1) / ROWS_PER_BLOCK;
    geg_kernel<<<blocks, ROWS_PER_BLOCK>>>(x, out, n);
}